// round 2
// baseline (speedup 1.0000x reference)
#include <cuda_runtime.h>
#include <cuda_bf16.h>

#define NN 100000
#define NE 600000
#define NG 128
#define NHEAD 4
#define HID 32

// -------- device scratch (no allocation allowed) --------
__device__ float    g_h1[NN * 128];
__device__ float    g_num1[NN * 128];
__device__ float    g_als1[NN * 4];
__device__ float    g_ald1[NN * 4];
__device__ unsigned g_emax1[NN * 4];
__device__ float    g_esum1[NN * 4];

__device__ float    g_h2[NN * 32];
__device__ float    g_num2[NN * 32];
__device__ float    g_als2[NN];
__device__ float    g_ald2[NN];
__device__ unsigned g_emax2[NN];
__device__ float    g_esum2[NN];

__device__ float    g_pool[NG * 32];
__device__ float    g_cnt[NG];

// order-preserving float<->uint for atomicMax on floats
__device__ __forceinline__ unsigned f2o(float f) {
    unsigned u = __float_as_uint(f);
    return (u & 0x80000000u) ? ~u : (u | 0x80000000u);
}
__device__ __forceinline__ float o2f(unsigned u) {
    return (u & 0x80000000u) ? __uint_as_float(u & 0x7fffffffu)
                             : __uint_as_float(~u);
}
__device__ __forceinline__ float lrelu(float x) { return x > 0.f ? x : 0.2f * x; }

// ---------------- K0: zero pool accumulators ----------------
__global__ void k_zero_pool() {
    int i = blockIdx.x * blockDim.x + threadIdx.x;
    if (i < NG * 32) g_pool[i] = 0.f;
    if (i < NG) g_cnt[i] = 0.f;
}

// ---------------- K1: node phase, layer 1 ----------------
// h1 = x @ W1 ; als/ald ; emax init with self-loop e ; zero accumulators
__global__ void k1(const float* __restrict__ x, const float* __restrict__ W1,
                   const float* __restrict__ as1, const float* __restrict__ ad1) {
    int i = blockIdx.x;
    int t = threadIdx.x;          // 0..127 = head*32 + c
    float x0 = x[i * 4 + 0], x1 = x[i * 4 + 1], x2 = x[i * 4 + 2], x3 = x[i * 4 + 3];
    float h = x0 * W1[t] + x1 * W1[128 + t] + x2 * W1[256 + t] + x3 * W1[384 + t];
    g_h1[i * 128 + t] = h;
    g_num1[i * 128 + t] = 0.f;
    int head = t >> 5, lane = t & 31;
    float ps = h * as1[t];
    float pd = h * ad1[t];
#pragma unroll
    for (int o = 16; o; o >>= 1) {
        ps += __shfl_xor_sync(0xffffffffu, ps, o);
        pd += __shfl_xor_sync(0xffffffffu, pd, o);
    }
    if (lane == 0) {
        g_als1[i * 4 + head] = ps;
        g_ald1[i * 4 + head] = pd;
        float e = lrelu(ps + pd);           // self-loop score seeds the max
        g_emax1[i * 4 + head] = f2o(e);
        g_esum1[i * 4 + head] = 0.f;
    }
}

// ---------------- K2: edge max, layer 1 ----------------
__global__ void k2(const int* __restrict__ ei) {
    long long idx = (long long)blockIdx.x * blockDim.x + threadIdx.x;
    if (idx >= (long long)NE * 4) return;
    int e = (int)(idx >> 2), h = (int)(idx & 3);
    int s = ei[e], d = ei[NE + e];
    float ev = lrelu(g_als1[s * 4 + h] + g_ald1[d * 4 + h]);
    atomicMax(&g_emax1[d * 4 + h], f2o(ev));
}

// ---------------- K3: edge scatter, layer 1 (warp per edge) ----------------
__global__ void k3(const int* __restrict__ ei) {
    int e = blockIdx.x * 8 + (threadIdx.x >> 5);
    if (e >= NE) return;
    int lane = threadIdx.x & 31;
    int s = ei[e], d = ei[NE + e];
    float ex[4];
#pragma unroll
    for (int h = 0; h < 4; h++) {
        float ev = lrelu(g_als1[s * 4 + h] + g_ald1[d * 4 + h]);
        float m = o2f(g_emax1[d * 4 + h]);
        ex[h] = __expf(ev - m);
    }
    if (lane < 4) atomicAdd(&g_esum1[d * 4 + lane], ex[lane]);
#pragma unroll
    for (int h = 0; h < 4; h++) {
        float v = g_h1[s * 128 + h * 32 + lane] * ex[h];
        atomicAdd(&g_num1[d * 128 + h * 32 + lane], v);
    }
}

// ---------------- K4: node phase, layer 1 finalize + layer 2 setup ----------------
__global__ void k4(const float* __restrict__ b1, const float* __restrict__ W2,
                   const float* __restrict__ as2, const float* __restrict__ ad2) {
    __shared__ float sh[128];
    int i = blockIdx.x, t = threadIdx.x, head = t >> 5;
    float als = g_als1[i * 4 + head], ald = g_ald1[i * 4 + head];
    float es = lrelu(als + ald);
    float m = o2f(g_emax1[i * 4 + head]);
    float exs = __expf(es - m);                    // self-loop contribution
    float denom = g_esum1[i * 4 + head] + exs;
    float v = (g_num1[i * 128 + t] + g_h1[i * 128 + t] * exs) / denom + b1[t];
    v = v > 0.f ? v : expm1f(v);                   // ELU
    sh[t] = v;
    __syncthreads();
    if (t < 32) {
        float acc = 0.f;
#pragma unroll 8
        for (int k = 0; k < 128; k++) acc += sh[k] * W2[k * 32 + t];
        g_h2[i * 32 + t] = acc;
        g_num2[i * 32 + t] = 0.f;
        float ps = acc * as2[t];
        float pd = acc * ad2[t];
#pragma unroll
        for (int o = 16; o; o >>= 1) {
            ps += __shfl_xor_sync(0xffffffffu, ps, o);
            pd += __shfl_xor_sync(0xffffffffu, pd, o);
        }
        if (t == 0) {
            g_als2[i] = ps;
            g_ald2[i] = pd;
            g_emax2[i] = f2o(lrelu(ps + pd));
            g_esum2[i] = 0.f;
        }
    }
}

// ---------------- K5: edge max, layer 2 ----------------
__global__ void k5(const int* __restrict__ ei) {
    int e = blockIdx.x * blockDim.x + threadIdx.x;
    if (e >= NE) return;
    int s = ei[e], d = ei[NE + e];
    float ev = lrelu(g_als2[s] + g_ald2[d]);
    atomicMax(&g_emax2[d], f2o(ev));
}

// ---------------- K6: edge scatter, layer 2 (warp per edge) ----------------
__global__ void k6(const int* __restrict__ ei) {
    int e = blockIdx.x * 8 + (threadIdx.x >> 5);
    if (e >= NE) return;
    int lane = threadIdx.x & 31;
    int s = ei[e], d = ei[NE + e];
    float ev = lrelu(g_als2[s] + g_ald2[d]);
    float m = o2f(g_emax2[d]);
    float ex = __expf(ev - m);
    if (lane == 0) atomicAdd(&g_esum2[d], ex);
    atomicAdd(&g_num2[d * 32 + lane], g_h2[s * 32 + lane] * ex);
}

// ---------------- K7: finalize layer 2 + pool scatter (warp per node) ----------------
__global__ void k7(const float* __restrict__ b2, const int* __restrict__ batch) {
    int i = blockIdx.x * 8 + (threadIdx.x >> 5);
    if (i >= NN) return;
    int lane = threadIdx.x & 31;
    float als = g_als2[i], ald = g_ald2[i];
    float es = lrelu(als + ald);
    float m = o2f(g_emax2[i]);
    float exs = __expf(es - m);
    float denom = g_esum2[i] + exs;
    float v = (g_num2[i * 32 + lane] + g_h2[i * 32 + lane] * exs) / denom + b2[lane];
    v = v > 0.f ? v : expm1f(v);                   // ELU
    int b = batch[i];
    atomicAdd(&g_pool[b * 32 + lane], v);
    if (lane == 0) atomicAdd(&g_cnt[b], 1.0f);
}

// ---------------- K8: mean pool + MLP head + sigmoid ----------------
__global__ void k8(const float* __restrict__ Wc1, const float* __restrict__ bc1,
                   const float* __restrict__ Wc2, const float* __restrict__ bc2,
                   float* __restrict__ out) {
    int g = threadIdx.x;
    if (g >= NG) return;
    float cnt = g_cnt[g];
    cnt = cnt > 1.f ? cnt : 1.f;
    float gm[32];
#pragma unroll
    for (int c = 0; c < 32; c++) gm[c] = g_pool[g * 32 + c] / cnt;
    float acc2 = bc2[0];
#pragma unroll 4
    for (int c = 0; c < 32; c++) {
        float z = bc1[c];
#pragma unroll
        for (int k = 0; k < 32; k++) z += gm[k] * Wc1[k * 32 + c];
        z = z > 0.f ? z : 0.f;
        acc2 += z * Wc2[c];
    }
    out[g] = 1.f / (1.f + expf(-acc2));
}

extern "C" void kernel_launch(void* const* d_in, const int* in_sizes, int n_in,
                              void* d_out, int out_size) {
    const float* x     = (const float*)d_in[0];
    const int*   ei    = (const int*)d_in[1];     // int32 (JAX x64 disabled downcasts int64)
    const int*   batch = (const int*)d_in[2];
    const float* W1    = (const float*)d_in[3];
    const float* as1   = (const float*)d_in[4];
    const float* ad1   = (const float*)d_in[5];
    const float* b1    = (const float*)d_in[6];
    const float* W2    = (const float*)d_in[7];
    const float* as2   = (const float*)d_in[8];
    const float* ad2   = (const float*)d_in[9];
    const float* b2    = (const float*)d_in[10];
    const float* Wc1   = (const float*)d_in[11];
    const float* bc1   = (const float*)d_in[12];
    const float* Wc2   = (const float*)d_in[13];
    const float* bc2   = (const float*)d_in[14];
    float* out = (float*)d_out;

    k_zero_pool<<<(NG * 32 + 255) / 256, 256>>>();
    k1<<<NN, 128>>>(x, W1, as1, ad1);
    k2<<<(NE * 4 + 255) / 256, 256>>>(ei);
    k3<<<(NE + 7) / 8, 256>>>(ei);
    k4<<<NN, 128>>>(b1, W2, as2, ad2);
    k5<<<(NE + 255) / 256, 256>>>(ei);
    k6<<<(NE + 7) / 8, 256>>>(ei);
    k7<<<(NN + 7) / 8, 256>>>(b2, batch);
    k8<<<1, 128>>>(Wc1, bc1, Wc2, bc2, out);
}

// round 3
// speedup vs baseline: 1.7186x; 1.7186x over previous
#include <cuda_runtime.h>
#include <cuda_bf16.h>

#define NN 100000
#define NE 600000
#define NG 128
#define CAP 64      // adjacency slots per node (Poisson(6) max deg ~25)

// -------- device scratch --------
__device__ float g_h1[NN * 128];
__device__ float g_als1[NN * 4];
__device__ float g_ald1[NN * 4];
__device__ float g_h2[NN * 32];
__device__ float g_als2[NN];
__device__ float g_ald2[NN];
__device__ int   g_deg[NN];
__device__ int   g_adj[NN * CAP];
__device__ float g_pool[NG * 32];
__device__ float g_cnt[NG];

__device__ __forceinline__ float lrelu(float x) { return x > 0.f ? x : 0.2f * x; }

// ---------------- K0: zero deg + pool ----------------
__global__ void k_zero() {
    int i = blockIdx.x * blockDim.x + threadIdx.x;
    if (i < NN) g_deg[i] = 0;
    if (i < NG * 32) g_pool[i] = 0.f;
    if (i < NG) g_cnt[i] = 0.f;
}

// ---------------- KB: build dst-bucketed adjacency ----------------
__global__ void k_build(const int* __restrict__ ei) {
    int e = blockIdx.x * blockDim.x + threadIdx.x;
    if (e >= NE) return;
    int s = ei[e], d = ei[NE + e];
    int slot = atomicAdd(&g_deg[d], 1);
    if (slot < CAP) g_adj[d * CAP + slot] = s;
}

// ---------------- K1: node GEMM layer 1 ----------------
__global__ void k1(const float* __restrict__ x, const float* __restrict__ W1,
                   const float* __restrict__ as1, const float* __restrict__ ad1) {
    int i = blockIdx.x;
    int t = threadIdx.x;          // 0..127 = head*32 + c
    float x0 = x[i * 4 + 0], x1 = x[i * 4 + 1], x2 = x[i * 4 + 2], x3 = x[i * 4 + 3];
    float h = x0 * W1[t] + x1 * W1[128 + t] + x2 * W1[256 + t] + x3 * W1[384 + t];
    g_h1[i * 128 + t] = h;
    int head = t >> 5, lane = t & 31;
    float ps = h * as1[t];
    float pd = h * ad1[t];
#pragma unroll
    for (int o = 16; o; o >>= 1) {
        ps += __shfl_xor_sync(0xffffffffu, ps, o);
        pd += __shfl_xor_sync(0xffffffffu, pd, o);
    }
    if (lane == 0) {
        g_als1[i * 4 + head] = ps;
        g_ald1[i * 4 + head] = pd;
    }
}

// ---------------- A1: layer-1 gather-aggregate + finalize + GEMM -> h2, als2, ald2 ----------------
// warp per dst node; 8 warps / block; W2 staged in shared
__global__ void __launch_bounds__(256, 4) agg1(const float* __restrict__ b1,
                                               const float* __restrict__ W2,
                                               const float* __restrict__ as2,
                                               const float* __restrict__ ad2) {
    __shared__ float sW2[128 * 32];
    __shared__ float sv[8][128];
    int tid = threadIdx.x;
#pragma unroll
    for (int k = tid; k < 128 * 32; k += 256) sW2[k] = W2[k];
    __syncthreads();

    int w = tid >> 5, lane = tid & 31;
    int i = blockIdx.x * 8 + w;
    if (i >= NN) return;

    int deg = g_deg[i];
    if (deg > CAP) deg = CAP;
    const float4 aldv = *(const float4*)&g_als1[0 + i * 4 + 0 * 0];  // placeholder avoided below
    // destination-side scores (broadcast loads)
    float4 ald_d = *(const float4*)&g_ald1[i * 4];
    float4 als_i = *(const float4*)&g_als1[i * 4];
    (void)aldv;

    // self-loop term
    float exs0 = __expf(lrelu(als_i.x + ald_d.x));
    float exs1 = __expf(lrelu(als_i.y + ald_d.y));
    float exs2 = __expf(lrelu(als_i.z + ald_d.z));
    float exs3 = __expf(lrelu(als_i.w + ald_d.w));
    float den0 = exs0, den1 = exs1, den2 = exs2, den3 = exs3;
    float acc0 = 0.f, acc1 = 0.f, acc2 = 0.f, acc3 = 0.f;

    for (int base = 0; base < deg; base += 32) {
        int cnt = deg - base; if (cnt > 32) cnt = 32;
        int a = (lane < cnt) ? g_adj[i * CAP + base + lane] : 0;
        for (int j = 0; j < cnt; ++j) {
            int s = __shfl_sync(0xffffffffu, a, j);
            float4 als_s = *(const float4*)&g_als1[s * 4];
            float ex0 = __expf(lrelu(als_s.x + ald_d.x));
            float ex1 = __expf(lrelu(als_s.y + ald_d.y));
            float ex2 = __expf(lrelu(als_s.z + ald_d.z));
            float ex3 = __expf(lrelu(als_s.w + ald_d.w));
            den0 += ex0; den1 += ex1; den2 += ex2; den3 += ex3;
            const float* hp = &g_h1[s * 128];
            acc0 += hp[lane]       * ex0;
            acc1 += hp[32 + lane]  * ex1;
            acc2 += hp[64 + lane]  * ex2;
            acc3 += hp[96 + lane]  * ex3;
        }
    }

    const float* hi = &g_h1[i * 128];
    float v0 = (hi[lane]      * exs0 + acc0) / den0 + b1[lane];
    float v1 = (hi[32 + lane] * exs1 + acc1) / den1 + b1[32 + lane];
    float v2 = (hi[64 + lane] * exs2 + acc2) / den2 + b1[64 + lane];
    float v3 = (hi[96 + lane] * exs3 + acc3) / den3 + b1[96 + lane];
    v0 = v0 > 0.f ? v0 : expm1f(v0);
    v1 = v1 > 0.f ? v1 : expm1f(v1);
    v2 = v2 > 0.f ? v2 : expm1f(v2);
    v3 = v3 > 0.f ? v3 : expm1f(v3);
    sv[w][lane] = v0; sv[w][32 + lane] = v1; sv[w][64 + lane] = v2; sv[w][96 + lane] = v3;
    __syncwarp();

    // GEMM 128 -> 32 (lane = output channel)
    float h2v = 0.f;
#pragma unroll 8
    for (int k = 0; k < 128; ++k) h2v += sv[w][k] * sW2[k * 32 + lane];
    g_h2[i * 32 + lane] = h2v;

    float ps = h2v * as2[lane];
    float pd = h2v * ad2[lane];
#pragma unroll
    for (int o = 16; o; o >>= 1) {
        ps += __shfl_xor_sync(0xffffffffu, ps, o);
        pd += __shfl_xor_sync(0xffffffffu, pd, o);
    }
    if (lane == 0) { g_als2[i] = ps; g_ald2[i] = pd; }
}

// ---------------- A2: layer-2 gather-aggregate + finalize + pool ----------------
__global__ void __launch_bounds__(256, 6) agg2(const float* __restrict__ b2,
                                               const int* __restrict__ batch) {
    int w = threadIdx.x >> 5, lane = threadIdx.x & 31;
    int i = blockIdx.x * 8 + w;
    if (i >= NN) return;

    int deg = g_deg[i];
    if (deg > CAP) deg = CAP;
    float ald_i = g_ald2[i];
    float exs = __expf(lrelu(g_als2[i] + ald_i));
    float den = exs;
    float acc = 0.f;

    for (int base = 0; base < deg; base += 32) {
        int cnt = deg - base; if (cnt > 32) cnt = 32;
        int a = (lane < cnt) ? g_adj[i * CAP + base + lane] : 0;
        for (int j = 0; j < cnt; ++j) {
            int s = __shfl_sync(0xffffffffu, a, j);
            float ex = __expf(lrelu(g_als2[s] + ald_i));
            den += ex;
            acc += g_h2[s * 32 + lane] * ex;
        }
    }

    float v = (g_h2[i * 32 + lane] * exs + acc) / den + b2[lane];
    v = v > 0.f ? v : expm1f(v);
    int b = batch[i];
    atomicAdd(&g_pool[b * 32 + lane], v);
    if (lane == 0) atomicAdd(&g_cnt[b], 1.0f);
}

// ---------------- K8: mean pool + MLP head + sigmoid ----------------
__global__ void k8(const float* __restrict__ Wc1, const float* __restrict__ bc1,
                   const float* __restrict__ Wc2, const float* __restrict__ bc2,
                   float* __restrict__ out) {
    int g = threadIdx.x;
    if (g >= NG) return;
    float cnt = g_cnt[g];
    cnt = cnt > 1.f ? cnt : 1.f;
    float gm[32];
#pragma unroll
    for (int c = 0; c < 32; c++) gm[c] = g_pool[g * 32 + c] / cnt;
    float acc2 = bc2[0];
#pragma unroll 4
    for (int c = 0; c < 32; c++) {
        float z = bc1[c];
#pragma unroll
        for (int k = 0; k < 32; k++) z += gm[k] * Wc1[k * 32 + c];
        z = z > 0.f ? z : 0.f;
        acc2 += z * Wc2[c];
    }
    out[g] = 1.f / (1.f + expf(-acc2));
}

extern "C" void kernel_launch(void* const* d_in, const int* in_sizes, int n_in,
                              void* d_out, int out_size) {
    const float* x     = (const float*)d_in[0];
    const int*   ei    = (const int*)d_in[1];
    const int*   batch = (const int*)d_in[2];
    const float* W1    = (const float*)d_in[3];
    const float* as1   = (const float*)d_in[4];
    const float* ad1   = (const float*)d_in[5];
    const float* b1    = (const float*)d_in[6];
    const float* W2    = (const float*)d_in[7];
    const float* as2   = (const float*)d_in[8];
    const float* ad2   = (const float*)d_in[9];
    const float* b2    = (const float*)d_in[10];
    const float* Wc1   = (const float*)d_in[11];
    const float* bc1   = (const float*)d_in[12];
    const float* Wc2   = (const float*)d_in[13];
    const float* bc2   = (const float*)d_in[14];
    float* out = (float*)d_out;

    k_zero<<<(NN + 255) / 256, 256>>>();
    k1<<<NN, 128>>>(x, W1, as1, ad1);
    k_build<<<(NE + 255) / 256, 256>>>(ei);
    agg1<<<(NN + 7) / 8, 256>>>(b1, W2, as2, ad2);
    agg2<<<(NN + 7) / 8, 256>>>(b2, batch);
    k8<<<1, 128>>>(Wc1, bc1, Wc2, bc2, out);
}

// round 4
// speedup vs baseline: 1.8699x; 1.0881x over previous
#include <cuda_runtime.h>
#include <cuda_bf16.h>

#define NN 100000
#define NE 600000
#define NG 128
#define CAP 64      // adjacency slots per node (Poisson(6): P(deg>64) ~ 0)

// -------- device scratch --------
__device__ __align__(16) float g_als1[NN * 4];
__device__ __align__(16) float g_ald1[NN * 4];
__device__ __align__(16) float g_w4[NN * 16];   // per-node, per-head weighted-x / den
__device__ float g_h2[NN * 32];
__device__ float g_als2[NN];
__device__ float g_ald2[NN];
__device__ int   g_deg[NN];
__device__ int   g_adj[CAP * NN];               // slot-major: adj[slot*NN + dst]
__device__ float g_pool[NG * 32];
__device__ float g_cnt[NG];

__device__ __forceinline__ float lrelu(float x) { return x > 0.f ? x : 0.2f * x; }

// ---------------- K0: zero deg + pool ----------------
__global__ void k_zero() {
    int i = blockIdx.x * blockDim.x + threadIdx.x;
    if (i < NN) g_deg[i] = 0;
    if (i < NG * 32) g_pool[i] = 0.f;
    if (i < NG) g_cnt[i] = 0.f;
}

// ---------------- KB: build dst-bucketed adjacency (slot-major) ----------------
__global__ void k_build(const int* __restrict__ ei) {
    int e = blockIdx.x * blockDim.x + threadIdx.x;
    if (e >= NE) return;
    int s = ei[e], d = ei[NE + e];
    int slot = atomicAdd(&g_deg[d], 1);
    if (slot < CAP) g_adj[slot * NN + d] = s;
}

// ---------------- K1: attention scores, layer 1 (h1 kept in registers) ----------------
__global__ void k1(const float* __restrict__ x, const float* __restrict__ W1,
                   const float* __restrict__ as1, const float* __restrict__ ad1) {
    int i = blockIdx.x;
    int t = threadIdx.x;          // 0..127 = head*32 + c
    float x0 = x[i * 4 + 0], x1 = x[i * 4 + 1], x2 = x[i * 4 + 2], x3 = x[i * 4 + 3];
    float h = x0 * W1[t] + x1 * W1[128 + t] + x2 * W1[256 + t] + x3 * W1[384 + t];
    int head = t >> 5, lane = t & 31;
    float ps = h * as1[t];
    float pd = h * ad1[t];
#pragma unroll
    for (int o = 16; o; o >>= 1) {
        ps += __shfl_xor_sync(0xffffffffu, ps, o);
        pd += __shfl_xor_sync(0xffffffffu, pd, o);
    }
    if (lane == 0) {
        g_als1[i * 4 + head] = ps;
        g_ald1[i * 4 + head] = pd;
    }
}

// ---------------- AGG-A: layer-1 edge aggregation in x-space (thread per node) ----------------
// num[h,:] = (Sum_e ex_e * x[s_e]) @ W1[:, h-block]  -> only accumulate 4-vectors per head
__global__ void aggA(const float* __restrict__ x) {
    int i = blockIdx.x * blockDim.x + threadIdx.x;
    if (i >= NN) return;
    const float4* x4 = (const float4*)x;

    float4 xi   = x4[i];
    float4 alsi = *(const float4*)&g_als1[i * 4];
    float4 aldi = *(const float4*)&g_ald1[i * 4];

    // self-loop seeds
    float ex0 = __expf(lrelu(alsi.x + aldi.x));
    float ex1 = __expf(lrelu(alsi.y + aldi.y));
    float ex2 = __expf(lrelu(alsi.z + aldi.z));
    float ex3 = __expf(lrelu(alsi.w + aldi.w));
    float den0 = ex0, den1 = ex1, den2 = ex2, den3 = ex3;
    float a00 = ex0*xi.x, a01 = ex0*xi.y, a02 = ex0*xi.z, a03 = ex0*xi.w;
    float a10 = ex1*xi.x, a11 = ex1*xi.y, a12 = ex1*xi.z, a13 = ex1*xi.w;
    float a20 = ex2*xi.x, a21 = ex2*xi.y, a22 = ex2*xi.z, a23 = ex2*xi.w;
    float a30 = ex3*xi.x, a31 = ex3*xi.y, a32 = ex3*xi.z, a33 = ex3*xi.w;

    int deg = g_deg[i];
    if (deg > CAP) deg = CAP;
    for (int e = 0; e < deg; ++e) {
        int s = g_adj[e * NN + i];                 // coalesced across threads
        float4 xs   = x4[s];
        float4 alss = *(const float4*)&g_als1[s * 4];
        float e0 = __expf(lrelu(alss.x + aldi.x));
        float e1 = __expf(lrelu(alss.y + aldi.y));
        float e2 = __expf(lrelu(alss.z + aldi.z));
        float e3 = __expf(lrelu(alss.w + aldi.w));
        den0 += e0; den1 += e1; den2 += e2; den3 += e3;
        a00 += e0*xs.x; a01 += e0*xs.y; a02 += e0*xs.z; a03 += e0*xs.w;
        a10 += e1*xs.x; a11 += e1*xs.y; a12 += e1*xs.z; a13 += e1*xs.w;
        a20 += e2*xs.x; a21 += e2*xs.y; a22 += e2*xs.z; a23 += e2*xs.w;
        a30 += e3*xs.x; a31 += e3*xs.y; a32 += e3*xs.z; a33 += e3*xs.w;
    }
    float r0 = 1.f/den0, r1 = 1.f/den1, r2 = 1.f/den2, r3 = 1.f/den3;
    float4* out = (float4*)&g_w4[i * 16];
    out[0] = make_float4(a00*r0, a01*r0, a02*r0, a03*r0);
    out[1] = make_float4(a10*r1, a11*r1, a12*r1, a13*r1);
    out[2] = make_float4(a20*r2, a21*r2, a22*r2, a23*r2);
    out[3] = make_float4(a30*r3, a31*r3, a32*r3, a33*r3);
}

// ---------------- AGG-B: apply W1, bias, ELU, then 128->32 GEMM (warp per node) ----------------
__global__ void __launch_bounds__(256) aggB(const float* __restrict__ W1,
                                            const float* __restrict__ b1,
                                            const float* __restrict__ W2,
                                            const float* __restrict__ as2,
                                            const float* __restrict__ ad2) {
    __shared__ float sW2[128 * 32];
    __shared__ float sW1[512];
    __shared__ float sv[8][128];
    int tid = threadIdx.x;
    for (int k = tid; k < 128 * 32; k += 256) sW2[k] = W2[k];
    for (int k = tid; k < 512; k += 256) sW1[k] = W1[k];
    __syncthreads();

    int w = tid >> 5, lane = tid & 31;
    int i = blockIdx.x * 8 + w;
    if (i >= NN) return;

    const float4* w4 = (const float4*)&g_w4[i * 16];
#pragma unroll
    for (int h = 0; h < 4; ++h) {
        float4 a = w4[h];                          // broadcast load
        int ch = h * 32 + lane;
        float v = a.x * sW1[ch] + a.y * sW1[128 + ch] +
                  a.z * sW1[256 + ch] + a.w * sW1[384 + ch] + b1[ch];
        v = v > 0.f ? v : expm1f(v);               // ELU
        sv[w][ch] = v;
    }
    __syncwarp();

    float h2v = 0.f;
#pragma unroll 16
    for (int k = 0; k < 128; ++k) h2v += sv[w][k] * sW2[k * 32 + lane];
    g_h2[i * 32 + lane] = h2v;

    float ps = h2v * as2[lane];
    float pd = h2v * ad2[lane];
#pragma unroll
    for (int o = 16; o; o >>= 1) {
        ps += __shfl_xor_sync(0xffffffffu, ps, o);
        pd += __shfl_xor_sync(0xffffffffu, pd, o);
    }
    if (lane == 0) { g_als2[i] = ps; g_ald2[i] = pd; }
}

// ---------------- AGG-2: layer-2 gather + finalize + pool (warp per node) ----------------
__global__ void __launch_bounds__(256) agg2(const float* __restrict__ b2,
                                            const int* __restrict__ batch) {
    int w = threadIdx.x >> 5, lane = threadIdx.x & 31;
    int i = blockIdx.x * 8 + w;
    if (i >= NN) return;

    int deg = g_deg[i];
    if (deg > CAP) deg = CAP;
    float ald_i = g_ald2[i];
    float exs = __expf(lrelu(g_als2[i] + ald_i));
    float den = exs;
    float acc = 0.f;

    for (int base = 0; base < deg; base += 32) {
        int cnt = deg - base; if (cnt > 32) cnt = 32;
        int a = 0; float exl = 0.f;
        if (lane < cnt) {
            a = g_adj[(base + lane) * NN + i];
            exl = __expf(lrelu(g_als2[a] + ald_i));   // one exp per edge (per lane)
        }
        float dsum = exl;
#pragma unroll
        for (int o = 16; o; o >>= 1) dsum += __shfl_xor_sync(0xffffffffu, dsum, o);
        den += dsum;
        for (int j = 0; j < cnt; ++j) {
            int   s  = __shfl_sync(0xffffffffu, a, j);
            float ex = __shfl_sync(0xffffffffu, exl, j);
            acc += g_h2[s * 32 + lane] * ex;          // coalesced 128B
        }
    }

    float v = (g_h2[i * 32 + lane] * exs + acc) / den + b2[lane];
    v = v > 0.f ? v : expm1f(v);
    int b = batch[i];
    atomicAdd(&g_pool[b * 32 + lane], v);
    if (lane == 0) atomicAdd(&g_cnt[b], 1.0f);
}

// ---------------- K8: mean pool + MLP head + sigmoid ----------------
__global__ void k8(const float* __restrict__ Wc1, const float* __restrict__ bc1,
                   const float* __restrict__ Wc2, const float* __restrict__ bc2,
                   float* __restrict__ out) {
    int g = threadIdx.x;
    if (g >= NG) return;
    float cnt = g_cnt[g];
    cnt = cnt > 1.f ? cnt : 1.f;
    float gm[32];
#pragma unroll
    for (int c = 0; c < 32; c++) gm[c] = g_pool[g * 32 + c] / cnt;
    float acc2 = bc2[0];
#pragma unroll 4
    for (int c = 0; c < 32; c++) {
        float z = bc1[c];
#pragma unroll
        for (int k = 0; k < 32; k++) z += gm[k] * Wc1[k * 32 + c];
        z = z > 0.f ? z : 0.f;
        acc2 += z * Wc2[c];
    }
    out[g] = 1.f / (1.f + expf(-acc2));
}

extern "C" void kernel_launch(void* const* d_in, const int* in_sizes, int n_in,
                              void* d_out, int out_size) {
    const float* x     = (const float*)d_in[0];
    const int*   ei    = (const int*)d_in[1];
    const int*   batch = (const int*)d_in[2];
    const float* W1    = (const float*)d_in[3];
    const float* as1   = (const float*)d_in[4];
    const float* ad1   = (const float*)d_in[5];
    const float* b1    = (const float*)d_in[6];
    const float* W2    = (const float*)d_in[7];
    const float* as2   = (const float*)d_in[8];
    const float* ad2   = (const float*)d_in[9];
    const float* b2    = (const float*)d_in[10];
    const float* Wc1   = (const float*)d_in[11];
    const float* bc1   = (const float*)d_in[12];
    const float* Wc2   = (const float*)d_in[13];
    const float* bc2   = (const float*)d_in[14];
    float* out = (float*)d_out;

    k_zero<<<(NN + 255) / 256, 256>>>();
    k1<<<NN, 128>>>(x, W1, as1, ad1);
    k_build<<<(NE + 255) / 256, 256>>>(ei);
    aggA<<<(NN + 255) / 256, 256>>>(x);
    aggB<<<(NN + 7) / 8, 256>>>(W1, b1, W2, as2, ad2);
    agg2<<<(NN + 7) / 8, 256>>>(b2, batch);
    k8<<<1, 128>>>(Wc1, bc1, Wc2, bc2, out);
}

// round 5
// speedup vs baseline: 2.4554x; 1.3131x over previous
#include <cuda_runtime.h>
#include <cuda_bf16.h>

#define NN 100000
#define NE 600000
#define NG 128
#define CAP 64      // adjacency slots per node (Poisson(6): P(deg>64) ~ 0)

// -------- device scratch --------
__device__ __align__(16) float g_als1[NN * 4];
__device__ __align__(16) float g_ald1[NN * 4];
__device__ __align__(16) float g_w4[NN * 16];   // per-node, per-head weighted-x / den
__device__ float g_h2[NN * 32];
__device__ float g_als2[NN];
__device__ float g_ald2[NN];
__device__ int   g_deg[NN];
__device__ int   g_adj[CAP * NN];               // slot-major: adj[slot*NN + dst]
__device__ float g_pool[NG * 32];
__device__ float g_cnt[NG];
__device__ __align__(16) float g_Ws[16];        // 4x4: W1 folded with a_s1
__device__ __align__(16) float g_Wd[16];        // 4x4: W1 folded with a_d1

__device__ __forceinline__ float lrelu(float x) { return x > 0.f ? x : 0.2f * x; }

// ---------------- KP: precompute 4x4 folded score matrices + zero pool ----------------
__global__ void kP(const float* __restrict__ W1, const float* __restrict__ as1,
                   const float* __restrict__ ad1) {
    int t = threadIdx.x;                 // 0..255
    if (t < 16) {
        int d = t >> 2, h = t & 3;
        float s = 0.f, dd = 0.f;
#pragma unroll
        for (int c = 0; c < 32; ++c) {
            float w = W1[d * 128 + h * 32 + c];
            s += w * as1[h * 32 + c];
            dd += w * ad1[h * 32 + c];
        }
        g_Ws[d * 4 + h] = s;
        g_Wd[d * 4 + h] = dd;
    }
    int i = blockIdx.x * blockDim.x + t;
    if (i < NG * 32) g_pool[i] = 0.f;
    if (i < NG) g_cnt[i] = 0.f;
}

// ---------------- K0: zero deg ----------------
__global__ void k_zero() {
    int i = blockIdx.x * blockDim.x + threadIdx.x;
    if (i < NN) g_deg[i] = 0;
}

// ---------------- KB: build dst-bucketed adjacency (slot-major) ----------------
__global__ void k_build(const int* __restrict__ ei) {
    int e = blockIdx.x * blockDim.x + threadIdx.x;
    if (e >= NE) return;
    int s = ei[e], d = ei[NE + e];
    int slot = atomicAdd(&g_deg[d], 1);
    if (slot < CAP) g_adj[slot * NN + d] = s;
}

// ---------------- K1: attention scores via folded 4x4 (thread per node) ----------------
__global__ void k1(const float* __restrict__ x) {
    int i = blockIdx.x * blockDim.x + threadIdx.x;
    if (i >= NN) return;
    float4 xi = ((const float4*)x)[i];
    const float4* Ws = (const float4*)g_Ws;     // row d -> 4 heads
    const float4* Wd = (const float4*)g_Wd;
    float4 w0 = Ws[0], w1 = Ws[1], w2 = Ws[2], w3 = Ws[3];
    float4 s;
    s.x = xi.x*w0.x + xi.y*w1.x + xi.z*w2.x + xi.w*w3.x;
    s.y = xi.x*w0.y + xi.y*w1.y + xi.z*w2.y + xi.w*w3.y;
    s.z = xi.x*w0.z + xi.y*w1.z + xi.z*w2.z + xi.w*w3.z;
    s.w = xi.x*w0.w + xi.y*w1.w + xi.z*w2.w + xi.w*w3.w;
    ((float4*)g_als1)[i] = s;
    w0 = Wd[0]; w1 = Wd[1]; w2 = Wd[2]; w3 = Wd[3];
    float4 d;
    d.x = xi.x*w0.x + xi.y*w1.x + xi.z*w2.x + xi.w*w3.x;
    d.y = xi.x*w0.y + xi.y*w1.y + xi.z*w2.y + xi.w*w3.y;
    d.z = xi.x*w0.z + xi.y*w1.z + xi.z*w2.z + xi.w*w3.z;
    d.w = xi.x*w0.w + xi.y*w1.w + xi.z*w2.w + xi.w*w3.w;
    ((float4*)g_ald1)[i] = d;
}

// ---------------- AGG-A: layer-1 edge aggregation in x-space (thread per node) ----------------
__global__ void aggA(const float* __restrict__ x) {
    int i = blockIdx.x * blockDim.x + threadIdx.x;
    if (i >= NN) return;
    const float4* x4 = (const float4*)x;

    float4 xi   = x4[i];
    float4 alsi = ((const float4*)g_als1)[i];
    float4 aldi = ((const float4*)g_ald1)[i];

    float ex0 = __expf(lrelu(alsi.x + aldi.x));
    float ex1 = __expf(lrelu(alsi.y + aldi.y));
    float ex2 = __expf(lrelu(alsi.z + aldi.z));
    float ex3 = __expf(lrelu(alsi.w + aldi.w));
    float den0 = ex0, den1 = ex1, den2 = ex2, den3 = ex3;
    float a00 = ex0*xi.x, a01 = ex0*xi.y, a02 = ex0*xi.z, a03 = ex0*xi.w;
    float a10 = ex1*xi.x, a11 = ex1*xi.y, a12 = ex1*xi.z, a13 = ex1*xi.w;
    float a20 = ex2*xi.x, a21 = ex2*xi.y, a22 = ex2*xi.z, a23 = ex2*xi.w;
    float a30 = ex3*xi.x, a31 = ex3*xi.y, a32 = ex3*xi.z, a33 = ex3*xi.w;

    int deg = g_deg[i];
    if (deg > CAP) deg = CAP;
    for (int e = 0; e < deg; ++e) {
        int s = g_adj[e * NN + i];                 // coalesced across threads
        float4 xs   = x4[s];
        float4 alss = ((const float4*)g_als1)[s];
        float e0 = __expf(lrelu(alss.x + aldi.x));
        float e1 = __expf(lrelu(alss.y + aldi.y));
        float e2 = __expf(lrelu(alss.z + aldi.z));
        float e3 = __expf(lrelu(alss.w + aldi.w));
        den0 += e0; den1 += e1; den2 += e2; den3 += e3;
        a00 += e0*xs.x; a01 += e0*xs.y; a02 += e0*xs.z; a03 += e0*xs.w;
        a10 += e1*xs.x; a11 += e1*xs.y; a12 += e1*xs.z; a13 += e1*xs.w;
        a20 += e2*xs.x; a21 += e2*xs.y; a22 += e2*xs.z; a23 += e2*xs.w;
        a30 += e3*xs.x; a31 += e3*xs.y; a32 += e3*xs.z; a33 += e3*xs.w;
    }
    float r0 = 1.f/den0, r1 = 1.f/den1, r2 = 1.f/den2, r3 = 1.f/den3;
    float4* out = (float4*)&g_w4[i * 16];
    out[0] = make_float4(a00*r0, a01*r0, a02*r0, a03*r0);
    out[1] = make_float4(a10*r1, a11*r1, a12*r1, a13*r1);
    out[2] = make_float4(a20*r2, a21*r2, a22*r2, a23*r2);
    out[3] = make_float4(a30*r3, a31*r3, a32*r3, a33*r3);
}

// ---------------- AGG-B: W1 + bias + ELU + 128->32 GEMM (grid-stride, warp per node) ----------------
__global__ void __launch_bounds__(256) aggB(const float* __restrict__ W1,
                                            const float* __restrict__ b1,
                                            const float* __restrict__ W2,
                                            const float* __restrict__ as2,
                                            const float* __restrict__ ad2) {
    __shared__ float sW2[128 * 32];
    __shared__ float sW1[512];
    __shared__ float sb1[128];
    __shared__ float sv[8][128];
    int tid = threadIdx.x;
    for (int k = tid; k < 128 * 32; k += 256) sW2[k] = W2[k];
    for (int k = tid; k < 512; k += 256) sW1[k] = W1[k];
    if (tid < 128) sb1[tid] = b1[tid];
    __syncthreads();

    int w = tid >> 5, lane = tid & 31;
    float a2s = as2[lane], a2d = ad2[lane];

    for (int i0 = blockIdx.x * 8; i0 < NN; i0 += gridDim.x * 8) {
        int i = i0 + w;
        if (i >= NN) break;

        const float4* w4 = (const float4*)&g_w4[i * 16];
#pragma unroll
        for (int h = 0; h < 4; ++h) {
            float4 a = w4[h];                      // broadcast load
            int ch = h * 32 + lane;
            float v = a.x * sW1[ch] + a.y * sW1[128 + ch] +
                      a.z * sW1[256 + ch] + a.w * sW1[384 + ch] + sb1[ch];
            v = v > 0.f ? v : expm1f(v);           // ELU
            sv[w][ch] = v;
        }
        __syncwarp();

        float h2v = 0.f;
#pragma unroll 16
        for (int k = 0; k < 128; ++k) h2v += sv[w][k] * sW2[k * 32 + lane];
        g_h2[i * 32 + lane] = h2v;

        float ps = h2v * a2s;
        float pd = h2v * a2d;
#pragma unroll
        for (int o = 16; o; o >>= 1) {
            ps += __shfl_xor_sync(0xffffffffu, ps, o);
            pd += __shfl_xor_sync(0xffffffffu, pd, o);
        }
        if (lane == 0) { g_als2[i] = ps; g_ald2[i] = pd; }
        __syncwarp();
    }
}

// ---------------- AGG-2: layer-2 gather + finalize + pool (warp per node) ----------------
__global__ void __launch_bounds__(256) agg2(const float* __restrict__ b2,
                                            const int* __restrict__ batch) {
    int w = threadIdx.x >> 5, lane = threadIdx.x & 31;
    int i = blockIdx.x * 8 + w;
    if (i >= NN) return;

    int deg = g_deg[i];
    if (deg > CAP) deg = CAP;
    float ald_i = g_ald2[i];
    float exs = __expf(lrelu(g_als2[i] + ald_i));
    float den = exs;
    float acc = 0.f;

    for (int base = 0; base < deg; base += 32) {
        int cnt = deg - base; if (cnt > 32) cnt = 32;
        int a = 0; float exl = 0.f;
        if (lane < cnt) {
            a = g_adj[(base + lane) * NN + i];
            exl = __expf(lrelu(g_als2[a] + ald_i));   // one exp per edge (per lane)
        }
        float dsum = exl;
#pragma unroll
        for (int o = 16; o; o >>= 1) dsum += __shfl_xor_sync(0xffffffffu, dsum, o);
        den += dsum;
        for (int j = 0; j < cnt; ++j) {
            int   s  = __shfl_sync(0xffffffffu, a, j);
            float ex = __shfl_sync(0xffffffffu, exl, j);
            acc += g_h2[s * 32 + lane] * ex;          // coalesced 128B
        }
    }

    float v = (g_h2[i * 32 + lane] * exs + acc) / den + b2[lane];
    v = v > 0.f ? v : expm1f(v);
    int b = batch[i];
    atomicAdd(&g_pool[b * 32 + lane], v);
    if (lane == 0) atomicAdd(&g_cnt[b], 1.0f);
}

// ---------------- K8: mean pool + MLP head + sigmoid ----------------
__global__ void k8(const float* __restrict__ Wc1, const float* __restrict__ bc1,
                   const float* __restrict__ Wc2, const float* __restrict__ bc2,
                   float* __restrict__ out) {
    int g = threadIdx.x;
    if (g >= NG) return;
    float cnt = g_cnt[g];
    cnt = cnt > 1.f ? cnt : 1.f;
    float gm[32];
#pragma unroll
    for (int c = 0; c < 32; c++) gm[c] = g_pool[g * 32 + c] / cnt;
    float acc2 = bc2[0];
#pragma unroll 4
    for (int c = 0; c < 32; c++) {
        float z = bc1[c];
#pragma unroll
        for (int k = 0; k < 32; k++) z += gm[k] * Wc1[k * 32 + c];
        z = z > 0.f ? z : 0.f;
        acc2 += z * Wc2[c];
    }
    out[g] = 1.f / (1.f + expf(-acc2));
}

extern "C" void kernel_launch(void* const* d_in, const int* in_sizes, int n_in,
                              void* d_out, int out_size) {
    const float* x     = (const float*)d_in[0];
    const int*   ei    = (const int*)d_in[1];
    const int*   batch = (const int*)d_in[2];
    const float* W1    = (const float*)d_in[3];
    const float* as1   = (const float*)d_in[4];
    const float* ad1   = (const float*)d_in[5];
    const float* b1    = (const float*)d_in[6];
    const float* W2    = (const float*)d_in[7];
    const float* as2   = (const float*)d_in[8];
    const float* ad2   = (const float*)d_in[9];
    const float* b2    = (const float*)d_in[10];
    const float* Wc1   = (const float*)d_in[11];
    const float* bc1   = (const float*)d_in[12];
    const float* Wc2   = (const float*)d_in[13];
    const float* bc2   = (const float*)d_in[14];
    float* out = (float*)d_out;

    kP<<<16, 256>>>(W1, as1, ad1);
    k_zero<<<(NN + 255) / 256, 256>>>();
    k1<<<(NN + 255) / 256, 256>>>(x);
    k_build<<<(NE + 255) / 256, 256>>>(ei);
    aggA<<<(NN + 255) / 256, 256>>>(x);
    aggB<<<592, 256>>>(W1, b1, W2, as2, ad2);
    agg2<<<(NN + 7) / 8, 256>>>(b2, batch);
    k8<<<1, 128>>>(Wc1, bc1, Wc2, bc2, out);
}

// round 6
// speedup vs baseline: 2.7077x; 1.1027x over previous
#include <cuda_runtime.h>
#include <cuda_bf16.h>

#define NN 100000
#define NE 600000
#define NG 128
#define CAP 64      // adjacency slots per node (Poisson(6): P(deg>64) ~ 0)

// -------- device scratch --------
__device__ __align__(16) float g_als1[NN * 4];
__device__ __align__(16) float g_ald1[NN * 4];
__device__ __align__(16) float g_w4[NN * 16];   // per-node, per-head weighted-x / den
__device__ float g_h2[NN * 32];
__device__ float g_als2[NN];
__device__ float g_ald2[NN];
__device__ int   g_deg[NN];
__device__ int   g_adj[CAP * NN];               // slot-major: adj[slot*NN + dst]
__device__ float g_pool[NG * 32];
__device__ float g_cnt[NG];

__device__ __forceinline__ float lrelu(float x) { return x > 0.f ? x : 0.2f * x; }
__device__ __forceinline__ float elu(float x) { return x > 0.f ? x : (__expf(x) - 1.f); }

// ---------------- K0: zero deg + pool ----------------
__global__ void k_zero() {
    int i = blockIdx.x * blockDim.x + threadIdx.x;
    if (i < NN) g_deg[i] = 0;
    if (i < NG * 32) g_pool[i] = 0.f;
    if (i < NG) g_cnt[i] = 0.f;
}

// ---------------- KB: build dst-bucketed adjacency (slot-major) ----------------
__global__ void k_build(const int* __restrict__ ei) {
    int e = blockIdx.x * blockDim.x + threadIdx.x;
    if (e >= NE) return;
    int s = ei[e], d = ei[NE + e];
    int slot = atomicAdd(&g_deg[d], 1);
    if (slot < CAP) g_adj[slot * NN + d] = s;
}

// ---------------- K1: attention scores via per-block folded 4x4 ----------------
__global__ void k1(const float* __restrict__ x, const float* __restrict__ W1,
                   const float* __restrict__ as1, const float* __restrict__ ad1) {
    __shared__ float sWs[16], sWd[16];     // [d*4+h]
    int t = threadIdx.x;
    if (t < 32) {
        int d = (t & 15) >> 2, h = t & 3;
        const float* av = (t < 16) ? as1 : ad1;
        float s = 0.f;
#pragma unroll
        for (int c = 0; c < 32; ++c) s += W1[d * 128 + h * 32 + c] * av[h * 32 + c];
        if (t < 16) sWs[t] = s; else sWd[t - 16] = s;
    }
    __syncthreads();
    int i = blockIdx.x * blockDim.x + t;
    if (i >= NN) return;
    float4 xi = ((const float4*)x)[i];
    float4 s, d;
    s.x = xi.x*sWs[0] + xi.y*sWs[4] + xi.z*sWs[8]  + xi.w*sWs[12];
    s.y = xi.x*sWs[1] + xi.y*sWs[5] + xi.z*sWs[9]  + xi.w*sWs[13];
    s.z = xi.x*sWs[2] + xi.y*sWs[6] + xi.z*sWs[10] + xi.w*sWs[14];
    s.w = xi.x*sWs[3] + xi.y*sWs[7] + xi.z*sWs[11] + xi.w*sWs[15];
    d.x = xi.x*sWd[0] + xi.y*sWd[4] + xi.z*sWd[8]  + xi.w*sWd[12];
    d.y = xi.x*sWd[1] + xi.y*sWd[5] + xi.z*sWd[9]  + xi.w*sWd[13];
    d.z = xi.x*sWd[2] + xi.y*sWd[6] + xi.z*sWd[10] + xi.w*sWd[14];
    d.w = xi.x*sWd[3] + xi.y*sWd[7] + xi.z*sWd[11] + xi.w*sWd[15];
    ((float4*)g_als1)[i] = s;
    ((float4*)g_ald1)[i] = d;
}

// ---------------- AGG-A: layer-1 edge aggregation in x-space (thread per node) ----------------
__global__ void aggA(const float* __restrict__ x) {
    int i = blockIdx.x * blockDim.x + threadIdx.x;
    if (i >= NN) return;
    const float4* x4 = (const float4*)x;

    float4 xi   = x4[i];
    float4 alsi = ((const float4*)g_als1)[i];
    float4 aldi = ((const float4*)g_ald1)[i];

    float ex0 = __expf(lrelu(alsi.x + aldi.x));
    float ex1 = __expf(lrelu(alsi.y + aldi.y));
    float ex2 = __expf(lrelu(alsi.z + aldi.z));
    float ex3 = __expf(lrelu(alsi.w + aldi.w));
    float den0 = ex0, den1 = ex1, den2 = ex2, den3 = ex3;
    float a00 = ex0*xi.x, a01 = ex0*xi.y, a02 = ex0*xi.z, a03 = ex0*xi.w;
    float a10 = ex1*xi.x, a11 = ex1*xi.y, a12 = ex1*xi.z, a13 = ex1*xi.w;
    float a20 = ex2*xi.x, a21 = ex2*xi.y, a22 = ex2*xi.z, a23 = ex2*xi.w;
    float a30 = ex3*xi.x, a31 = ex3*xi.y, a32 = ex3*xi.z, a33 = ex3*xi.w;

    int deg = g_deg[i];
    if (deg > CAP) deg = CAP;
    for (int e = 0; e < deg; ++e) {
        int s = g_adj[e * NN + i];                 // coalesced across threads
        float4 xs   = x4[s];
        float4 alss = ((const float4*)g_als1)[s];
        float e0 = __expf(lrelu(alss.x + aldi.x));
        float e1 = __expf(lrelu(alss.y + aldi.y));
        float e2 = __expf(lrelu(alss.z + aldi.z));
        float e3 = __expf(lrelu(alss.w + aldi.w));
        den0 += e0; den1 += e1; den2 += e2; den3 += e3;
        a00 += e0*xs.x; a01 += e0*xs.y; a02 += e0*xs.z; a03 += e0*xs.w;
        a10 += e1*xs.x; a11 += e1*xs.y; a12 += e1*xs.z; a13 += e1*xs.w;
        a20 += e2*xs.x; a21 += e2*xs.y; a22 += e2*xs.z; a23 += e2*xs.w;
        a30 += e3*xs.x; a31 += e3*xs.y; a32 += e3*xs.z; a33 += e3*xs.w;
    }
    float r0 = 1.f/den0, r1 = 1.f/den1, r2 = 1.f/den2, r3 = 1.f/den3;
    float4* out = (float4*)&g_w4[i * 16];
    out[0] = make_float4(a00*r0, a01*r0, a02*r0, a03*r0);
    out[1] = make_float4(a10*r1, a11*r1, a12*r1, a13*r1);
    out[2] = make_float4(a20*r2, a21*r2, a22*r2, a23*r2);
    out[3] = make_float4(a30*r3, a31*r3, a32*r3, a33*r3);
}

// ---------------- AGG-B: W1 + bias + ELU + 128->32 GEMM (warp = 4 nodes, shuffle bcast) ----------------
__global__ void __launch_bounds__(256) aggB(const float* __restrict__ W1,
                                            const float* __restrict__ b1,
                                            const float* __restrict__ W2,
                                            const float* __restrict__ as2,
                                            const float* __restrict__ ad2) {
    __shared__ float sW2[128 * 32];
    int tid = threadIdx.x;
    for (int k = tid; k < 128 * 32; k += 256) sW2[k] = W2[k];
    __syncthreads();

    int w = tid >> 5, lane = tid & 31;
    // per-lane weight registers (loaded once)
    float W1r[4][4], b1r[4];
#pragma unroll
    for (int h = 0; h < 4; ++h) {
        b1r[h] = b1[h * 32 + lane];
#pragma unroll
        for (int d = 0; d < 4; ++d) W1r[d][h] = W1[d * 128 + h * 32 + lane];
    }
    float a2s = as2[lane], a2d = ad2[lane];

    int wg = blockIdx.x * 8 + w;                 // 592*8 = 4736 warps
    for (int g = wg; g < NN / 4; g += 4736) {
        int i0 = g * 4;
        float v[4][4];
#pragma unroll
        for (int n = 0; n < 4; ++n) {
            const float4* w4 = (const float4*)&g_w4[(i0 + n) * 16];
#pragma unroll
            for (int h = 0; h < 4; ++h) {
                float4 a = w4[h];                 // broadcast load
                float t = a.x*W1r[0][h] + a.y*W1r[1][h] + a.z*W1r[2][h] + a.w*W1r[3][h] + b1r[h];
                v[n][h] = elu(t);
            }
        }
        float acc0 = 0.f, acc1 = 0.f, acc2 = 0.f, acc3 = 0.f;
#pragma unroll
        for (int h = 0; h < 4; ++h) {
#pragma unroll
            for (int j = 0; j < 32; ++j) {
                float w2v = sW2[(h * 32 + j) * 32 + lane];
                acc0 += __shfl_sync(0xffffffffu, v[0][h], j) * w2v;
                acc1 += __shfl_sync(0xffffffffu, v[1][h], j) * w2v;
                acc2 += __shfl_sync(0xffffffffu, v[2][h], j) * w2v;
                acc3 += __shfl_sync(0xffffffffu, v[3][h], j) * w2v;
            }
        }
        float accs[4] = {acc0, acc1, acc2, acc3};
#pragma unroll
        for (int n = 0; n < 4; ++n) {
            int i = i0 + n;
            g_h2[i * 32 + lane] = accs[n];
            float ps = accs[n] * a2s;
            float pd = accs[n] * a2d;
#pragma unroll
            for (int o = 16; o; o >>= 1) {
                ps += __shfl_xor_sync(0xffffffffu, ps, o);
                pd += __shfl_xor_sync(0xffffffffu, pd, o);
            }
            if (lane == 0) { g_als2[i] = ps; g_ald2[i] = pd; }
        }
    }
}

// ---------------- AGG-2: layer-2 gather + finalize + pool (warp per node) ----------------
__global__ void __launch_bounds__(256) agg2(const float* __restrict__ b2,
                                            const int* __restrict__ batch) {
    int w = threadIdx.x >> 5, lane = threadIdx.x & 31;
    int i = blockIdx.x * 8 + w;
    if (i >= NN) return;

    int deg = g_deg[i];
    if (deg > CAP) deg = CAP;
    float ald_i = g_ald2[i];
    float exs = __expf(lrelu(g_als2[i] + ald_i));
    float den = exs;
    float acc = 0.f;

    for (int base = 0; base < deg; base += 32) {
        int cnt = deg - base; if (cnt > 32) cnt = 32;
        int a = 0; float exl = 0.f;
        if (lane < cnt) {
            a = g_adj[(base + lane) * NN + i];
            exl = __expf(lrelu(g_als2[a] + ald_i));   // one exp per edge (per lane)
        }
        float dsum = exl;
#pragma unroll
        for (int o = 16; o; o >>= 1) dsum += __shfl_xor_sync(0xffffffffu, dsum, o);
        den += dsum;
        for (int j = 0; j < cnt; ++j) {
            int   s  = __shfl_sync(0xffffffffu, a, j);
            float ex = __shfl_sync(0xffffffffu, exl, j);
            acc += g_h2[s * 32 + lane] * ex;          // coalesced 128B
        }
    }

    float v = (g_h2[i * 32 + lane] * exs + acc) / den + b2[lane];
    v = elu(v);
    int b = batch[i];
    atomicAdd(&g_pool[b * 32 + lane], v);
    if (lane == 0) atomicAdd(&g_cnt[b], 1.0f);
}

// ---------------- K8: mean pool + MLP head + sigmoid ----------------
__global__ void k8(const float* __restrict__ Wc1, const float* __restrict__ bc1,
                   const float* __restrict__ Wc2, const float* __restrict__ bc2,
                   float* __restrict__ out) {
    int g = threadIdx.x;
    if (g >= NG) return;
    float cnt = g_cnt[g];
    cnt = cnt > 1.f ? cnt : 1.f;
    float gm[32];
#pragma unroll
    for (int c = 0; c < 32; c++) gm[c] = g_pool[g * 32 + c] / cnt;
    float acc2 = bc2[0];
#pragma unroll 4
    for (int c = 0; c < 32; c++) {
        float z = bc1[c];
#pragma unroll
        for (int k = 0; k < 32; k++) z += gm[k] * Wc1[k * 32 + c];
        z = z > 0.f ? z : 0.f;
        acc2 += z * Wc2[c];
    }
    out[g] = 1.f / (1.f + expf(-acc2));
}

extern "C" void kernel_launch(void* const* d_in, const int* in_sizes, int n_in,
                              void* d_out, int out_size) {
    const float* x     = (const float*)d_in[0];
    const int*   ei    = (const int*)d_in[1];
    const int*   batch = (const int*)d_in[2];
    const float* W1    = (const float*)d_in[3];
    const float* as1   = (const float*)d_in[4];
    const float* ad1   = (const float*)d_in[5];
    const float* b1    = (const float*)d_in[6];
    const float* W2    = (const float*)d_in[7];
    const float* as2   = (const float*)d_in[8];
    const float* ad2   = (const float*)d_in[9];
    const float* b2    = (const float*)d_in[10];
    const float* Wc1   = (const float*)d_in[11];
    const float* bc1   = (const float*)d_in[12];
    const float* Wc2   = (const float*)d_in[13];
    const float* bc2   = (const float*)d_in[14];
    float* out = (float*)d_out;

    k_zero<<<(NN + 255) / 256, 256>>>();
    k1<<<(NN + 255) / 256, 256>>>(x, W1, as1, ad1);
    k_build<<<(NE + 255) / 256, 256>>>(ei);
    aggA<<<(NN + 255) / 256, 256>>>(x);
    aggB<<<592, 256>>>(W1, b1, W2, as2, ad2);
    agg2<<<(NN + 7) / 8, 256>>>(b2, batch);
    k8<<<1, 128>>>(Wc1, bc1, Wc2, bc2, out);
}

// round 7
// speedup vs baseline: 3.1780x; 1.1737x over previous
#include <cuda_runtime.h>
#include <cuda_bf16.h>

#define NN 100000
#define NE 600000
#define NG 128
#define CAP 64      // adjacency slots per node (Poisson(6): P(deg>64) ~ 0)

// -------- device scratch --------
__device__ __align__(16) float g_als1[NN * 4];
__device__ __align__(16) float g_ald1[NN * 4];
__device__ __align__(16) float g_w4[NN * 16];   // per-node, per-head weighted-x / den
__device__ float g_h2[NN * 32];
__device__ float g_als2[NN];
__device__ float g_ald2[NN];
__device__ int   g_deg[NN];
__device__ int   g_adj[CAP * NN];               // slot-major: adj[slot*NN + dst]
__device__ float g_pool[NG * 32];
__device__ float g_cnt[NG];

__device__ __forceinline__ float lrelu(float x) { return x > 0.f ? x : 0.2f * x; }
__device__ __forceinline__ float elu(float x) { return x > 0.f ? x : (__expf(x) - 1.f); }

// ---------------- K1: zero deg/pool + attention scores via per-block folded 4x4 ----------------
__global__ void k1(const float* __restrict__ x, const float* __restrict__ W1,
                   const float* __restrict__ as1, const float* __restrict__ ad1) {
    __shared__ float sWs[16], sWd[16];     // [d*4+h]
    int t = threadIdx.x;
    if (t < 32) {
        int d = (t & 15) >> 2, h = t & 3;
        const float* av = (t < 16) ? as1 : ad1;
        float s = 0.f;
#pragma unroll
        for (int c = 0; c < 32; ++c) s += W1[d * 128 + h * 32 + c] * av[h * 32 + c];
        if (t < 16) sWs[t] = s; else sWd[t - 16] = s;
    }
    __syncthreads();
    int i = blockIdx.x * blockDim.x + t;
    if (i >= NN) return;
    g_deg[i] = 0;
    if (i < NG * 32) g_pool[i] = 0.f;
    if (i < NG) g_cnt[i] = 0.f;
    float4 xi = ((const float4*)x)[i];
    float4 s, d;
    s.x = xi.x*sWs[0] + xi.y*sWs[4] + xi.z*sWs[8]  + xi.w*sWs[12];
    s.y = xi.x*sWs[1] + xi.y*sWs[5] + xi.z*sWs[9]  + xi.w*sWs[13];
    s.z = xi.x*sWs[2] + xi.y*sWs[6] + xi.z*sWs[10] + xi.w*sWs[14];
    s.w = xi.x*sWs[3] + xi.y*sWs[7] + xi.z*sWs[11] + xi.w*sWs[15];
    d.x = xi.x*sWd[0] + xi.y*sWd[4] + xi.z*sWd[8]  + xi.w*sWd[12];
    d.y = xi.x*sWd[1] + xi.y*sWd[5] + xi.z*sWd[9]  + xi.w*sWd[13];
    d.z = xi.x*sWd[2] + xi.y*sWd[6] + xi.z*sWd[10] + xi.w*sWd[14];
    d.w = xi.x*sWd[3] + xi.y*sWd[7] + xi.z*sWd[11] + xi.w*sWd[15];
    ((float4*)g_als1)[i] = s;
    ((float4*)g_ald1)[i] = d;
}

// ---------------- KB: build dst-bucketed adjacency (slot-major) ----------------
__global__ void k_build(const int* __restrict__ ei) {
    int e = blockIdx.x * blockDim.x + threadIdx.x;
    if (e >= NE) return;
    int s = ei[e], d = ei[NE + e];
    int slot = atomicAdd(&g_deg[d], 1);
    if (slot < CAP) g_adj[slot * NN + d] = s;
}

// ---------------- AGG-A: layer-1 edge aggregation in x-space (thread per node) ----------------
__global__ void aggA(const float* __restrict__ x) {
    int i = blockIdx.x * blockDim.x + threadIdx.x;
    if (i >= NN) return;
    const float4* x4 = (const float4*)x;

    float4 xi   = x4[i];
    float4 alsi = ((const float4*)g_als1)[i];
    float4 aldi = ((const float4*)g_ald1)[i];

    float ex0 = __expf(lrelu(alsi.x + aldi.x));
    float ex1 = __expf(lrelu(alsi.y + aldi.y));
    float ex2 = __expf(lrelu(alsi.z + aldi.z));
    float ex3 = __expf(lrelu(alsi.w + aldi.w));
    float den0 = ex0, den1 = ex1, den2 = ex2, den3 = ex3;
    float a00 = ex0*xi.x, a01 = ex0*xi.y, a02 = ex0*xi.z, a03 = ex0*xi.w;
    float a10 = ex1*xi.x, a11 = ex1*xi.y, a12 = ex1*xi.z, a13 = ex1*xi.w;
    float a20 = ex2*xi.x, a21 = ex2*xi.y, a22 = ex2*xi.z, a23 = ex2*xi.w;
    float a30 = ex3*xi.x, a31 = ex3*xi.y, a32 = ex3*xi.z, a33 = ex3*xi.w;

    int deg = g_deg[i];
    if (deg > CAP) deg = CAP;
    for (int e = 0; e < deg; ++e) {
        int s = g_adj[e * NN + i];                 // coalesced across threads
        float4 xs   = x4[s];
        float4 alss = ((const float4*)g_als1)[s];
        float e0 = __expf(lrelu(alss.x + aldi.x));
        float e1 = __expf(lrelu(alss.y + aldi.y));
        float e2 = __expf(lrelu(alss.z + aldi.z));
        float e3 = __expf(lrelu(alss.w + aldi.w));
        den0 += e0; den1 += e1; den2 += e2; den3 += e3;
        a00 += e0*xs.x; a01 += e0*xs.y; a02 += e0*xs.z; a03 += e0*xs.w;
        a10 += e1*xs.x; a11 += e1*xs.y; a12 += e1*xs.z; a13 += e1*xs.w;
        a20 += e2*xs.x; a21 += e2*xs.y; a22 += e2*xs.z; a23 += e2*xs.w;
        a30 += e3*xs.x; a31 += e3*xs.y; a32 += e3*xs.z; a33 += e3*xs.w;
    }
    float r0 = 1.f/den0, r1 = 1.f/den1, r2 = 1.f/den2, r3 = 1.f/den3;
    float4* out = (float4*)&g_w4[i * 16];
    out[0] = make_float4(a00*r0, a01*r0, a02*r0, a03*r0);
    out[1] = make_float4(a10*r1, a11*r1, a12*r1, a13*r1);
    out[2] = make_float4(a20*r2, a21*r2, a22*r2, a23*r2);
    out[3] = make_float4(a30*r3, a31*r3, a32*r3, a33*r3);
}

// ---------------- AGG-B: W1 + bias + ELU + 128->32 GEMM (warp = 4 nodes, smem broadcast) ----------------
__global__ void __launch_bounds__(256) aggB(const float* __restrict__ W1,
                                            const float* __restrict__ b1,
                                            const float* __restrict__ W2,
                                            const float* __restrict__ as2,
                                            const float* __restrict__ ad2) {
    __shared__ float sW2[128 * 32];
    __shared__ __align__(16) float sv[8][4][128];   // [warp][node][k]
    int tid = threadIdx.x;
    for (int k = tid; k < 128 * 32; k += 256) sW2[k] = W2[k];
    __syncthreads();

    int w = tid >> 5, lane = tid & 31;
    // per-lane weight registers (loaded once)
    float W1r[4][4], b1r[4];
#pragma unroll
    for (int h = 0; h < 4; ++h) {
        b1r[h] = b1[h * 32 + lane];
#pragma unroll
        for (int d = 0; d < 4; ++d) W1r[d][h] = W1[d * 128 + h * 32 + lane];
    }
    float a2s = as2[lane], a2d = ad2[lane];

    int wg = blockIdx.x * 8 + w;                 // 592*8 = 4736 warps
    for (int g = wg; g < NN / 4; g += 4736) {
        int i0 = g * 4;
#pragma unroll
        for (int n = 0; n < 4; ++n) {
            const float4* w4 = (const float4*)&g_w4[(i0 + n) * 16];
#pragma unroll
            for (int h = 0; h < 4; ++h) {
                float4 a = w4[h];                 // broadcast load
                float t = a.x*W1r[0][h] + a.y*W1r[1][h] + a.z*W1r[2][h] + a.w*W1r[3][h] + b1r[h];
                sv[w][n][h * 32 + lane] = elu(t); // conflict-free STS
            }
        }
        __syncwarp();

        float acc0 = 0.f, acc1 = 0.f, acc2 = 0.f, acc3 = 0.f;
        const float4* v0 = (const float4*)sv[w][0];
        const float4* v1 = (const float4*)sv[w][1];
        const float4* v2 = (const float4*)sv[w][2];
        const float4* v3 = (const float4*)sv[w][3];
#pragma unroll
        for (int k4 = 0; k4 < 32; ++k4) {
            float4 a0 = v0[k4], a1 = v1[k4], a2 = v2[k4], a3 = v3[k4];  // LDS.128 broadcast
            float w2a = sW2[(k4 * 4 + 0) * 32 + lane];
            float w2b = sW2[(k4 * 4 + 1) * 32 + lane];
            float w2c = sW2[(k4 * 4 + 2) * 32 + lane];
            float w2d = sW2[(k4 * 4 + 3) * 32 + lane];
            acc0 += a0.x*w2a + a0.y*w2b + a0.z*w2c + a0.w*w2d;
            acc1 += a1.x*w2a + a1.y*w2b + a1.z*w2c + a1.w*w2d;
            acc2 += a2.x*w2a + a2.y*w2b + a2.z*w2c + a2.w*w2d;
            acc3 += a3.x*w2a + a3.y*w2b + a3.z*w2c + a3.w*w2d;
        }
        __syncwarp();

        float accs[4] = {acc0, acc1, acc2, acc3};
#pragma unroll
        for (int n = 0; n < 4; ++n) {
            int i = i0 + n;
            g_h2[i * 32 + lane] = accs[n];
            float ps = accs[n] * a2s;
            float pd = accs[n] * a2d;
#pragma unroll
            for (int o = 16; o; o >>= 1) {
                ps += __shfl_xor_sync(0xffffffffu, ps, o);
                pd += __shfl_xor_sync(0xffffffffu, pd, o);
            }
            if (lane == 0) { g_als2[i] = ps; g_ald2[i] = pd; }
        }
    }
}

// ---------------- AGG-2: layer-2 gather + finalize + pool (warp per node) ----------------
__global__ void __launch_bounds__(256) agg2(const float* __restrict__ b2,
                                            const int* __restrict__ batch) {
    int w = threadIdx.x >> 5, lane = threadIdx.x & 31;
    int i = blockIdx.x * 8 + w;
    if (i >= NN) return;

    int deg = g_deg[i];
    if (deg > CAP) deg = CAP;
    float ald_i = g_ald2[i];
    float exs = __expf(lrelu(g_als2[i] + ald_i));
    float den = exs;
    float acc = 0.f;

    for (int base = 0; base < deg; base += 32) {
        int cnt = deg - base; if (cnt > 32) cnt = 32;
        int a = 0; float exl = 0.f;
        if (lane < cnt) {
            a = g_adj[(base + lane) * NN + i];
            exl = __expf(lrelu(g_als2[a] + ald_i));   // one exp per edge (per lane)
        }
        float dsum = exl;
#pragma unroll
        for (int o = 16; o; o >>= 1) dsum += __shfl_xor_sync(0xffffffffu, dsum, o);
        den += dsum;
        for (int j = 0; j < cnt; ++j) {
            int   s  = __shfl_sync(0xffffffffu, a, j);
            float ex = __shfl_sync(0xffffffffu, exl, j);
            acc += g_h2[s * 32 + lane] * ex;          // coalesced 128B
        }
    }

    float v = (g_h2[i * 32 + lane] * exs + acc) / den + b2[lane];
    v = elu(v);
    int b = batch[i];
    atomicAdd(&g_pool[b * 32 + lane], v);
    if (lane == 0) atomicAdd(&g_cnt[b], 1.0f);
}

// ---------------- K8: mean pool + MLP head + sigmoid ----------------
__global__ void k8(const float* __restrict__ Wc1, const float* __restrict__ bc1,
                   const float* __restrict__ Wc2, const float* __restrict__ bc2,
                   float* __restrict__ out) {
    int g = threadIdx.x;
    if (g >= NG) return;
    float cnt = g_cnt[g];
    cnt = cnt > 1.f ? cnt : 1.f;
    float gm[32];
#pragma unroll
    for (int c = 0; c < 32; c++) gm[c] = g_pool[g * 32 + c] / cnt;
    float acc2 = bc2[0];
#pragma unroll 4
    for (int c = 0; c < 32; c++) {
        float z = bc1[c];
#pragma unroll
        for (int k = 0; k < 32; k++) z += gm[k] * Wc1[k * 32 + c];
        z = z > 0.f ? z : 0.f;
        acc2 += z * Wc2[c];
    }
    out[g] = 1.f / (1.f + expf(-acc2));
}

extern "C" void kernel_launch(void* const* d_in, const int* in_sizes, int n_in,
                              void* d_out, int out_size) {
    const float* x     = (const float*)d_in[0];
    const int*   ei    = (const int*)d_in[1];
    const int*   batch = (const int*)d_in[2];
    const float* W1    = (const float*)d_in[3];
    const float* as1   = (const float*)d_in[4];
    const float* ad1   = (const float*)d_in[5];
    const float* b1    = (const float*)d_in[6];
    const float* W2    = (const float*)d_in[7];
    const float* as2   = (const float*)d_in[8];
    const float* ad2   = (const float*)d_in[9];
    const float* b2    = (const float*)d_in[10];
    const float* Wc1   = (const float*)d_in[11];
    const float* bc1   = (const float*)d_in[12];
    const float* Wc2   = (const float*)d_in[13];
    const float* bc2   = (const float*)d_in[14];
    float* out = (float*)d_out;

    k1<<<(NN + 255) / 256, 256>>>(x, W1, as1, ad1);
    k_build<<<(NE + 255) / 256, 256>>>(ei);
    aggA<<<(NN + 255) / 256, 256>>>(x);
    aggB<<<592, 256>>>(W1, b1, W2, as2, ad2);
    agg2<<<(NN + 7) / 8, 256>>>(b2, batch);
    k8<<<1, 128>>>(Wc1, bc1, Wc2, bc2, out);
}

// round 8
// speedup vs baseline: 3.4781x; 1.0944x over previous
#include <cuda_runtime.h>
#include <cuda_bf16.h>

#define NN 100000
#define NE 600000
#define NG 128
#define CAP 64      // adjacency slots per node (Poisson(6): P(deg>64) ~ 0)

// -------- device scratch --------
__device__ __align__(16) float g_als1[NN * 4];
__device__ __align__(16) float g_ald1[NN * 4];
__device__ float g_h2[NN * 32];
__device__ float g_als2[NN];
__device__ float g_ald2[NN];
__device__ int   g_deg[NN];
__device__ int   g_adj[CAP * NN];               // slot-major: adj[slot*NN + dst]
__device__ float g_pool[NG * 32];
__device__ float g_cnt[NG];

__device__ __forceinline__ float lrelu(float x) { return x > 0.f ? x : 0.2f * x; }
__device__ __forceinline__ float elu(float x) { return x > 0.f ? x : (__expf(x) - 1.f); }

__device__ __forceinline__ unsigned long long packf2(float lo, float hi) {
    unsigned long long r;
    asm("mov.b64 %0, {%1, %2};" : "=l"(r) : "r"(__float_as_uint(lo)), "r"(__float_as_uint(hi)));
    return r;
}
__device__ __forceinline__ void unpackf2(float& lo, float& hi, unsigned long long v) {
    unsigned a, b;
    asm("mov.b64 {%0, %1}, %2;" : "=r"(a), "=r"(b) : "l"(v));
    lo = __uint_as_float(a); hi = __uint_as_float(b);
}
__device__ __forceinline__ void ffma2(unsigned long long& d, unsigned long long a, unsigned long long b) {
    asm("fma.rn.f32x2 %0, %1, %2, %0;" : "+l"(d) : "l"(a), "l"(b));
}

// ---------------- K1: zero deg/pool + attention scores via per-block folded 4x4 ----------------
__global__ void k1(const float* __restrict__ x, const float* __restrict__ W1,
                   const float* __restrict__ as1, const float* __restrict__ ad1) {
    __shared__ float sWs[16], sWd[16];     // [d*4+h]
    int t = threadIdx.x;
    if (t < 32) {
        int d = (t & 15) >> 2, h = t & 3;
        const float* av = (t < 16) ? as1 : ad1;
        float s = 0.f;
#pragma unroll
        for (int c = 0; c < 32; ++c) s += W1[d * 128 + h * 32 + c] * av[h * 32 + c];
        if (t < 16) sWs[t] = s; else sWd[t - 16] = s;
    }
    __syncthreads();
    int i = blockIdx.x * blockDim.x + t;
    if (i >= NN) return;
    g_deg[i] = 0;
    if (i < NG * 32) g_pool[i] = 0.f;
    if (i < NG) g_cnt[i] = 0.f;
    float4 xi = ((const float4*)x)[i];
    float4 s, d;
    s.x = xi.x*sWs[0] + xi.y*sWs[4] + xi.z*sWs[8]  + xi.w*sWs[12];
    s.y = xi.x*sWs[1] + xi.y*sWs[5] + xi.z*sWs[9]  + xi.w*sWs[13];
    s.z = xi.x*sWs[2] + xi.y*sWs[6] + xi.z*sWs[10] + xi.w*sWs[14];
    s.w = xi.x*sWs[3] + xi.y*sWs[7] + xi.z*sWs[11] + xi.w*sWs[15];
    d.x = xi.x*sWd[0] + xi.y*sWd[4] + xi.z*sWd[8]  + xi.w*sWd[12];
    d.y = xi.x*sWd[1] + xi.y*sWd[5] + xi.z*sWd[9]  + xi.w*sWd[13];
    d.z = xi.x*sWd[2] + xi.y*sWd[6] + xi.z*sWd[10] + xi.w*sWd[14];
    d.w = xi.x*sWd[3] + xi.y*sWd[7] + xi.z*sWd[11] + xi.w*sWd[15];
    ((float4*)g_als1)[i] = s;
    ((float4*)g_ald1)[i] = d;
}

// ---------------- KB: build dst-bucketed adjacency (slot-major) ----------------
__global__ void k_build(const int* __restrict__ ei) {
    int e = blockIdx.x * blockDim.x + threadIdx.x;
    if (e >= NE) return;
    int s = ei[e], d = ei[NE + e];
    int slot = atomicAdd(&g_deg[d], 1);
    if (slot < CAP) g_adj[slot * NN + d] = s;
}

// ---------------- AGG-F: fused layer-1 aggregate + W1/ELU + 128->32 GEMM (node per lane) ----------------
__global__ void __launch_bounds__(256) aggF(const float* __restrict__ x,
                                            const float* __restrict__ W1,
                                            const float* __restrict__ b1,
                                            const float* __restrict__ W2,
                                            const float* __restrict__ as2,
                                            const float* __restrict__ ad2) {
    __shared__ __align__(16) float sW1t[128 * 4];   // [ch][d]
    __shared__ float sb1[128];
    __shared__ __align__(16) float sW2[128 * 32];   // row-major [k][c]
    __shared__ float sas2[32], sad2[32];
    int tid = threadIdx.x;
    for (int k = tid; k < 128 * 32; k += 256) sW2[k] = W2[k];
    for (int k = tid; k < 512; k += 256) { int ch = k & 127, d = k >> 7; sW1t[ch * 4 + d] = W1[d * 128 + ch]; }
    if (tid < 128) sb1[tid] = b1[tid];
    if (tid < 32) { sas2[tid] = as2[tid]; sad2[tid] = ad2[tid]; }
    __syncthreads();

    int i = blockIdx.x * 256 + tid;
    if (i >= NN) return;

    // ---- phase 1: edge aggregation in x-space (as in aggA) ----
    const float4* x4 = (const float4*)x;
    float4 xi   = x4[i];
    float4 alsi = ((const float4*)g_als1)[i];
    float4 aldi = ((const float4*)g_ald1)[i];

    float ex0 = __expf(lrelu(alsi.x + aldi.x));
    float ex1 = __expf(lrelu(alsi.y + aldi.y));
    float ex2 = __expf(lrelu(alsi.z + aldi.z));
    float ex3 = __expf(lrelu(alsi.w + aldi.w));
    float den0 = ex0, den1 = ex1, den2 = ex2, den3 = ex3;
    float a00 = ex0*xi.x, a01 = ex0*xi.y, a02 = ex0*xi.z, a03 = ex0*xi.w;
    float a10 = ex1*xi.x, a11 = ex1*xi.y, a12 = ex1*xi.z, a13 = ex1*xi.w;
    float a20 = ex2*xi.x, a21 = ex2*xi.y, a22 = ex2*xi.z, a23 = ex2*xi.w;
    float a30 = ex3*xi.x, a31 = ex3*xi.y, a32 = ex3*xi.z, a33 = ex3*xi.w;

    int deg = g_deg[i];
    if (deg > CAP) deg = CAP;
    for (int e = 0; e < deg; ++e) {
        int s = g_adj[e * NN + i];
        float4 xs   = x4[s];
        float4 alss = ((const float4*)g_als1)[s];
        float e0 = __expf(lrelu(alss.x + aldi.x));
        float e1 = __expf(lrelu(alss.y + aldi.y));
        float e2 = __expf(lrelu(alss.z + aldi.z));
        float e3 = __expf(lrelu(alss.w + aldi.w));
        den0 += e0; den1 += e1; den2 += e2; den3 += e3;
        a00 += e0*xs.x; a01 += e0*xs.y; a02 += e0*xs.z; a03 += e0*xs.w;
        a10 += e1*xs.x; a11 += e1*xs.y; a12 += e1*xs.z; a13 += e1*xs.w;
        a20 += e2*xs.x; a21 += e2*xs.y; a22 += e2*xs.z; a23 += e2*xs.w;
        a30 += e3*xs.x; a31 += e3*xs.y; a32 += e3*xs.z; a33 += e3*xs.w;
    }
    float r0 = 1.f/den0, r1 = 1.f/den1, r2 = 1.f/den2, r3 = 1.f/den3;
    float4 w4h[4];
    w4h[0] = make_float4(a00*r0, a01*r0, a02*r0, a03*r0);
    w4h[1] = make_float4(a10*r1, a11*r1, a12*r1, a13*r1);
    w4h[2] = make_float4(a20*r2, a21*r2, a22*r2, a23*r2);
    w4h[3] = make_float4(a30*r3, a31*r3, a32*r3, a33*r3);

    // ---- phase 2: v = elu(w4 @ W1 + b1) ; acc = v @ W2  (packed f32x2) ----
    unsigned long long acc[16];
#pragma unroll
    for (int c2 = 0; c2 < 16; ++c2) acc[c2] = 0ULL;

#pragma unroll
    for (int h = 0; h < 4; ++h) {
        float4 a = w4h[h];
        float v32[32];
#pragma unroll
        for (int c = 0; c < 32; ++c) {
            float4 wc = ((const float4*)sW1t)[h * 32 + c];       // LDS.128 broadcast
            float t = a.x*wc.x + a.y*wc.y + a.z*wc.z + a.w*wc.w + sb1[h * 32 + c];
            v32[c] = elu(t);
        }
#pragma unroll
        for (int k = 0; k < 32; ++k) {
            unsigned long long vv = packf2(v32[k], v32[k]);
            const ulonglong2* w2p = (const ulonglong2*)&sW2[(h * 32 + k) * 32];
#pragma unroll
            for (int c4 = 0; c4 < 8; ++c4) {
                ulonglong2 q = w2p[c4];                           // LDS.128 broadcast
                ffma2(acc[c4 * 2],     vv, q.x);
                ffma2(acc[c4 * 2 + 1], vv, q.y);
            }
        }
    }

    // ---- epilogue: h2 store + layer-2 scores (per-lane, no reductions) ----
    float ps = 0.f, pd = 0.f;
    float h2v[32];
#pragma unroll
    for (int c2 = 0; c2 < 16; ++c2) {
        float lo, hi;
        unpackf2(lo, hi, acc[c2]);
        h2v[c2 * 2] = lo; h2v[c2 * 2 + 1] = hi;
        ps += lo * sas2[c2 * 2] + hi * sas2[c2 * 2 + 1];
        pd += lo * sad2[c2 * 2] + hi * sad2[c2 * 2 + 1];
    }
    float4* h2o = (float4*)&g_h2[i * 32];
#pragma unroll
    for (int c4 = 0; c4 < 8; ++c4)
        h2o[c4] = make_float4(h2v[c4*4], h2v[c4*4+1], h2v[c4*4+2], h2v[c4*4+3]);
    g_als2[i] = ps;
    g_ald2[i] = pd;
}

// ---------------- AGG-2: layer-2 gather + finalize + pool (warp per node) ----------------
__global__ void __launch_bounds__(256) agg2(const float* __restrict__ b2,
                                            const int* __restrict__ batch) {
    int w = threadIdx.x >> 5, lane = threadIdx.x & 31;
    int i = blockIdx.x * 8 + w;
    if (i >= NN) return;

    int deg = g_deg[i];
    if (deg > CAP) deg = CAP;
    float ald_i = g_ald2[i];
    float exs = __expf(lrelu(g_als2[i] + ald_i));
    float den = exs;
    float acc = 0.f;

    for (int base = 0; base < deg; base += 32) {
        int cnt = deg - base; if (cnt > 32) cnt = 32;
        int a = 0; float exl = 0.f;
        if (lane < cnt) {
            a = g_adj[(base + lane) * NN + i];
            exl = __expf(lrelu(g_als2[a] + ald_i));   // one exp per edge (per lane)
        }
        float dsum = exl;
#pragma unroll
        for (int o = 16; o; o >>= 1) dsum += __shfl_xor_sync(0xffffffffu, dsum, o);
        den += dsum;
        for (int j = 0; j < cnt; ++j) {
            int   s  = __shfl_sync(0xffffffffu, a, j);
            float ex = __shfl_sync(0xffffffffu, exl, j);
            acc += g_h2[s * 32 + lane] * ex;          // coalesced 128B
        }
    }

    float v = (g_h2[i * 32 + lane] * exs + acc) / den + b2[lane];
    v = elu(v);
    int b = batch[i];
    atomicAdd(&g_pool[b * 32 + lane], v);
    if (lane == 0) atomicAdd(&g_cnt[b], 1.0f);
}

// ---------------- K8: mean pool + MLP head + sigmoid ----------------
__global__ void k8(const float* __restrict__ Wc1, const float* __restrict__ bc1,
                   const float* __restrict__ Wc2, const float* __restrict__ bc2,
                   float* __restrict__ out) {
    int g = threadIdx.x;
    if (g >= NG) return;
    float cnt = g_cnt[g];
    cnt = cnt > 1.f ? cnt : 1.f;
    float gm[32];
#pragma unroll
    for (int c = 0; c < 32; c++) gm[c] = g_pool[g * 32 + c] / cnt;
    float acc2 = bc2[0];
#pragma unroll 4
    for (int c = 0; c < 32; c++) {
        float z = bc1[c];
#pragma unroll
        for (int k = 0; k < 32; k++) z += gm[k] * Wc1[k * 32 + c];
        z = z > 0.f ? z : 0.f;
        acc2 += z * Wc2[c];
    }
    out[g] = 1.f / (1.f + expf(-acc2));
}

extern "C" void kernel_launch(void* const* d_in, const int* in_sizes, int n_in,
                              void* d_out, int out_size) {
    const float* x     = (const float*)d_in[0];
    const int*   ei    = (const int*)d_in[1];
    const int*   batch = (const int*)d_in[2];
    const float* W1    = (const float*)d_in[3];
    const float* as1   = (const float*)d_in[4];
    const float* ad1   = (const float*)d_in[5];
    const float* b1    = (const float*)d_in[6];
    const float* W2    = (const float*)d_in[7];
    const float* as2   = (const float*)d_in[8];
    const float* ad2   = (const float*)d_in[9];
    const float* b2    = (const float*)d_in[10];
    const float* Wc1   = (const float*)d_in[11];
    const float* bc1   = (const float*)d_in[12];
    const float* Wc2   = (const float*)d_in[13];
    const float* bc2   = (const float*)d_in[14];
    float* out = (float*)d_out;

    k1<<<(NN + 255) / 256, 256>>>(x, W1, as1, ad1);
    k_build<<<(NE + 255) / 256, 256>>>(ei);
    aggF<<<(NN + 255) / 256, 256>>>(x, W1, b1, W2, as2, ad2);
    agg2<<<(NN + 7) / 8, 256>>>(b2, batch);
    k8<<<1, 128>>>(Wc1, bc1, Wc2, bc2, out);
}